// round 1
// baseline (speedup 1.0000x reference)
#include <cuda_runtime.h>
#include <cuda_bf16.h>
#include <math.h>

#define MAXV    2000000
#define NMESH   4

// Scratch: Lx (3 comps) + row_sum packed as float4 per row. 32 MB.
__device__ float4 d_acc[MAXV];
__device__ float  d_inv_nvpm[NMESH];

// ---------------------------------------------------------------------------
// Kernel 1: zero accumulator + output
// ---------------------------------------------------------------------------
__global__ void zero_kernel(float* __restrict__ out, int v) {
    const float4 z = make_float4(0.f, 0.f, 0.f, 0.f);
    int stride = gridDim.x * blockDim.x;
    for (int i = blockIdx.x * blockDim.x + threadIdx.x; i < v; i += stride)
        d_acc[i] = z;
    if (blockIdx.x == 0 && threadIdx.x == 0)
        out[0] = 0.f;
}

// ---------------------------------------------------------------------------
// Kernel 2: mesh vertex counts via binary search (verts_mesh_idx is sorted)
// ---------------------------------------------------------------------------
__global__ void mesh_count_kernel(const int* __restrict__ idx, int v) {
    int m = threadIdx.x;
    if (m >= NMESH) return;
    // lower_bound(value): first i with idx[i] >= value
    auto lb = [&](int val) {
        int lo = 0, hi = v;
        while (lo < hi) {
            int mid = (lo + hi) >> 1;
            if (__ldg(idx + mid) < val) lo = mid + 1; else hi = mid;
        }
        return lo;
    };
    int s = lb(m);
    int e = lb(m + 1);
    int cnt = e - s;
    d_inv_nvpm[m] = (cnt > 0) ? (1.f / (float)cnt) : 0.f;
}

// ---------------------------------------------------------------------------
// Kernel 3: COO scatter.  One thread handles 4 nnz (vectorized index/value
// loads), each nnz contributes one red.global.add.v4.f32.
// ---------------------------------------------------------------------------
__device__ __forceinline__ void red_add_v4(float4* addr, float x, float y,
                                           float z, float w) {
    asm volatile("red.global.add.v4.f32 [%0], {%1, %2, %3, %4};"
                 :: "l"(addr), "f"(x), "f"(y), "f"(z), "f"(w)
                 : "memory");
}

__device__ __forceinline__ void scatter_one(const float* __restrict__ verts,
                                            float v, int r, int c) {
    const float* p = verts + 3 * (long long)c;
    float px = __ldg(p + 0);
    float py = __ldg(p + 1);
    float pz = __ldg(p + 2);
    red_add_v4(&d_acc[r], v * px, v * py, v * pz, v);
}

__global__ void scatter_kernel(const float* __restrict__ vals,
                               const int*   __restrict__ rows,
                               const int*   __restrict__ cols,
                               const float* __restrict__ verts,
                               int nnz) {
    int t = blockIdx.x * blockDim.x + threadIdx.x;
    int base = t * 4;
    if (base + 3 < nnz) {
        float4 v = *reinterpret_cast<const float4*>(vals + base);
        int4   r = *reinterpret_cast<const int4*>(rows + base);
        int4   c = *reinterpret_cast<const int4*>(cols + base);
        scatter_one(verts, v.x, r.x, c.x);
        scatter_one(verts, v.y, r.y, c.y);
        scatter_one(verts, v.z, r.z, c.z);
        scatter_one(verts, v.w, r.w, c.w);
    } else {
        for (int i = base; i < nnz; i++)
            scatter_one(verts, __ldg(vals + i), __ldg(rows + i), __ldg(cols + i));
    }
}

// ---------------------------------------------------------------------------
// Kernel 4: per-vertex loss + global reduction
// ---------------------------------------------------------------------------
__global__ void finalize_kernel(const float* __restrict__ verts,
                                const int*   __restrict__ mesh_idx,
                                const float* __restrict__ coefs,
                                float* __restrict__ out,
                                int v) {
    int i = blockIdx.x * blockDim.x + threadIdx.x;
    float acc = 0.f;
    if (i < v) {
        float4 L = d_acc[i];
        float rs = L.w;
        float nw = (rs > 0.f) ? (1.f / rs) : rs;
        const float* p = verts + 3 * (long long)i;
        float rx = L.x * nw - __ldg(p + 0);
        float ry = L.y * nw - __ldg(p + 1);
        float rz = L.z * nw - __ldg(p + 2);
        float loss = sqrtf(rx * rx + ry * ry + rz * rz);
        float w = d_inv_nvpm[__ldg(mesh_idx + i)];
        acc = loss * w * __ldg(coefs + i) * (1.f / (float)NMESH);
    }

    // warp reduce
    #pragma unroll
    for (int off = 16; off > 0; off >>= 1)
        acc += __shfl_down_sync(0xFFFFFFFFu, acc, off);

    __shared__ float sdata[32];
    int lane = threadIdx.x & 31;
    int wid  = threadIdx.x >> 5;
    if (lane == 0) sdata[wid] = acc;
    __syncthreads();

    int nwarps = blockDim.x >> 5;
    if (wid == 0) {
        acc = (lane < nwarps) ? sdata[lane] : 0.f;
        #pragma unroll
        for (int off = 16; off > 0; off >>= 1)
            acc += __shfl_down_sync(0xFFFFFFFFu, acc, off);
        if (lane == 0)
            atomicAdd(out, acc);
    }
}

// ---------------------------------------------------------------------------
// Launch
// ---------------------------------------------------------------------------
extern "C" void kernel_launch(void* const* d_in, const int* in_sizes, int n_in,
                              void* d_out, int out_size) {
    const float* verts    = (const float*)d_in[0];
    const float* lap_vals = (const float*)d_in[1];
    const int*   lap_rows = (const int*)  d_in[2];
    const int*   lap_cols = (const int*)  d_in[3];
    const int*   mesh_idx = (const int*)  d_in[4];
    const float* coefs    = (const float*)d_in[5];
    float*       out      = (float*)d_out;

    int nnz = in_sizes[1];
    int v   = in_sizes[4];

    // 1. zero accumulator + output
    {
        int threads = 256;
        int blocks = (v + threads - 1) / threads;   // grid-stride anyway
        if (blocks > 8192) blocks = 8192;
        zero_kernel<<<blocks, threads>>>(out, v);
    }

    // 2. mesh counts (tiny)
    mesh_count_kernel<<<1, 32>>>(mesh_idx, v);

    // 3. scatter
    {
        int threads = 256;
        int quads = (nnz + 3) / 4;
        int blocks = (quads + threads - 1) / threads;
        scatter_kernel<<<blocks, threads>>>(lap_vals, lap_rows, lap_cols,
                                            verts, nnz);
    }

    // 4. finalize + reduce
    {
        int threads = 256;
        int blocks = (v + threads - 1) / threads;
        finalize_kernel<<<blocks, threads>>>(verts, mesh_idx, coefs, out, v);
    }
}